// round 14
// baseline (speedup 1.0000x reference)
#include <cuda_runtime.h>
#include <cuda_fp16.h>
#include <cstdint>

typedef unsigned int u32;
typedef __half half_t;

#define EDIM    256
#define MAXLOOP 16

// ---------------------------------------------------------------------------
// Global scratch (no allocation allowed)
// ---------------------------------------------------------------------------
__device__ half_t g_Q  [8192 * 256];       // fp16 Q (layer1, then layer2)
__device__ half_t g_KV [8192 * 512];       // layer1: K cols 0..255, V cols 256..511
__device__ half_t g_KV2[8192 * 512];       // layer2 K/V
__device__ float  g_X  [8192 * 256];
__device__ half_t g_Ac [8192 * 256];       // face activations fp16
__device__ half_t g_Ec [8192 * 256];       // edge activations fp16
__device__ half_t g_ATTc[8192 * 256];      // attention out fp16
__device__ half_t g_Wc1[768 * 256];        // layer1 in-proj weights fp16
__device__ half_t g_Wc2[768 * 256];        // layer2 in-proj weights fp16
__device__ half_t g_Wo1[256 * 256];
__device__ half_t g_Wo2[256 * 256];

// ---------------------------------------------------------------------------
// Helpers (plain sm_80+ features only — harness lowers to compute_103 PTX)
// ---------------------------------------------------------------------------
__device__ __forceinline__ u32 smem_u32(const void* p) {
    u32 a; asm("{ .reg .u64 t; cvta.to.shared.u64 t, %1; cvt.u32.u64 %0, t; }"
               : "=r"(a) : "l"(p));
    return a;
}
__device__ __forceinline__ void cpa16(u32 d, const void* s) {
    asm volatile("cp.async.ca.shared.global [%0], [%1], 16;" :: "r"(d), "l"(s));
}
#define CP_COMMIT() asm volatile("cp.async.commit_group;" ::: "memory")
#define CP_WAIT(n)  asm volatile("cp.async.wait_group %0;" :: "n"(n) : "memory")
#define LDSM4(r0, r1, r2, r3, a) \
    asm volatile("ldmatrix.sync.aligned.m8n8.x4.shared.b16 {%0,%1,%2,%3}, [%4];" \
                 : "=r"(r0), "=r"(r1), "=r"(r2), "=r"(r3) : "r"(a))

__device__ __forceinline__ void mma_f16(float* d, const u32* a, const u32* b) {
    asm volatile("mma.sync.aligned.m16n8k16.row.col.f32.f16.f16.f32 "
                 "{%0,%1,%2,%3}, {%4,%5,%6,%7}, {%8,%9}, {%0,%1,%2,%3};"
                 : "+f"(d[0]), "+f"(d[1]), "+f"(d[2]), "+f"(d[3])
                 : "r"(a[0]), "r"(a[1]), "r"(a[2]), "r"(a[3]),
                   "r"(b[0]), "r"(b[1]));
}

__device__ __forceinline__ u32 h2u(__half2 h) { return *reinterpret_cast<u32*>(&h); }
__device__ __forceinline__ __half2 u2h(u32 u) { return *reinterpret_cast<__half2*>(&u); }

__device__ __forceinline__ uint4 round8h(float4 f0, float4 f1) {
    return make_uint4(h2u(__floats2half2_rn(f0.x, f0.y)),
                      h2u(__floats2half2_rn(f0.z, f0.w)),
                      h2u(__floats2half2_rn(f1.x, f1.y)),
                      h2u(__floats2half2_rn(f1.z, f1.w)));
}

// ---------------------------------------------------------------------------
// conv_all: face, edge, w1, o1, w2, o2 fp32 -> fp16 (18432 rows, 2304 blocks)
// ---------------------------------------------------------------------------
__global__ void conv_all(const float* __restrict__ f, const float* __restrict__ e,
                         const float* __restrict__ w1, const float* __restrict__ o1,
                         const float* __restrict__ w2, const float* __restrict__ o2,
                         half_t* __restrict__ Ac, half_t* __restrict__ Ec,
                         half_t* __restrict__ W1, half_t* __restrict__ O1,
                         half_t* __restrict__ W2, half_t* __restrict__ O2)
{
    const int idx = blockIdx.x * 256 + threadIdx.x;
    int row = idx >> 5;
    const int c = (idx & 31) * 8;
    const float* src; half_t* dst;
    if      (row < 8192)  { src = f;  dst = Ac; }
    else if (row < 16384) { src = e;  dst = Ec; row -= 8192; }
    else if (row < 17152) { src = w1; dst = W1; row -= 16384; }
    else if (row < 17408) { src = o1; dst = O1; row -= 17152; }
    else if (row < 18176) { src = w2; dst = W2; row -= 17408; }
    else                  { src = o2; dst = O2; row -= 18176; }
    const float* s = src + (size_t)row * 256 + c;
    float4 f0 = *(const float4*)s, f1 = *(const float4*)(s + 4);
    *(uint4*)&dst[(size_t)row * 256 + c] = round8h(f0, f1);
}

// ---------------------------------------------------------------------------
// GEMM building blocks (K-chunk 64, 144B padded rows, warp tile 32x64)
// ---------------------------------------------------------------------------
template<int MB, int NB, int NTH>
__device__ __forceinline__ void load_chunk(u32 sb, const half_t* __restrict__ A,
                                           const half_t* __restrict__ B, int m0, int kc)
{
    const int tid = threadIdx.x;
    constexpr u32 AREG = MB * 144u;
#pragma unroll
    for (int i = tid; i < MB * 8; i += NTH) {
        const int r = i >> 3, s = i & 7;
        cpa16(sb + r * 144 + s * 16,
              A + ((size_t)(m0 + r) << 8) + kc * 64 + s * 8);
    }
#pragma unroll
    for (int i = tid; i < NB * 8; i += NTH) {
        const int r = i >> 3, s = i & 7;
        cpa16(sb + AREG + r * 144 + s * 16,
              B + ((size_t)r << 8) + kc * 64 + s * 8);
    }
}

// B-only loader (stage-2 of outln): 256 rows x 64 cols per chunk
template<int NTH>
__device__ __forceinline__ void load_b256(u32 dst, const half_t* __restrict__ B, int kc)
{
    const int tid = threadIdx.x;
#pragma unroll
    for (int i = tid; i < 256 * 8; i += NTH) {
        const int r = i >> 3, s = i & 7;
        cpa16(dst + r * 144 + s * 16, B + ((size_t)r << 8) + kc * 64 + s * 8);
    }
}

// warp tile 32x64, explicit A/B smem bases
__device__ __forceinline__ void mma_chunk(u32 aBase, u32 bBase, int wm, int wn,
                                          int lane, float c[2][8][4])
{
    const u32 arow  = lane & 15;
    const u32 ahalf = (lane >> 4) * 16;
#pragma unroll
    for (int ks = 0; ks < 4; ++ks) {
        const u32 kb = ks * 32 + ahalf;
        u32 ah[2][4];
#pragma unroll
        for (int t = 0; t < 2; ++t) {
            const u32 ad = aBase + (wm * 32 + t * 16 + arow) * 144 + kb;
            LDSM4(ah[t][0], ah[t][1], ah[t][2], ah[t][3], ad);
        }
#pragma unroll
        for (int p = 0; p < 4; ++p) {
            const u32 bd = bBase + (wn * 64 + p * 16 + arow) * 144 + kb;
            u32 m0r, m1r, m2r, m3r;
            LDSM4(m0r, m1r, m2r, m3r, bd);
            u32 b0[2] = { m0r, m2r }, b1[2] = { m1r, m3r };
#pragma unroll
            for (int t = 0; t < 2; ++t) {
                mma_f16(c[t][2 * p],     ah[t], b0);
                mma_f16(c[t][2 * p + 1], ah[t], b1);
            }
        }
    }
}

// full 128x128 KV-gemm body (2-stage K64 pipeline), fp16 out
__device__ __forceinline__ void kv_gemm_body(u32 sb, const half_t* __restrict__ A,
                                             const half_t* __restrict__ W,
                                             const float* __restrict__ bias,
                                             int m0, int n0, half_t* __restrict__ KVo)
{
    constexpr u32 CHUNK = (128 + 128) * 144u;
    const half_t* B = W + (size_t)n0 * 256;
    const int wid = threadIdx.x >> 5, lane = threadIdx.x & 31;
    const int wm = wid >> 1, wn = wid & 1;

    float c[2][8][4] = {};
    load_chunk<128, 128, 256>(sb, A, B, m0, 0);         CP_COMMIT();
    load_chunk<128, 128, 256>(sb + CHUNK, A, B, m0, 1); CP_COMMIT();
#pragma unroll
    for (int kc = 0; kc < 4; ++kc) {
        if (kc < 3) { CP_WAIT(1); } else { CP_WAIT(0); }
        __syncthreads();
        const u32 base = sb + (kc & 1) * CHUNK;
        mma_chunk(base, base + 128 * 144u, wm, wn, lane, c);
        __syncthreads();
        if (kc < 2) {
            load_chunk<128, 128, 256>(sb + (kc & 1) * CHUNK, A, B, m0, kc + 2);
            CP_COMMIT();
        }
    }
    const int cb = n0 - 256;
#pragma unroll
    for (int t = 0; t < 2; ++t)
#pragma unroll
        for (int u = 0; u < 8; ++u) {
            const int row = m0 + wm * 32 + t * 16 + (lane >> 2);
            const int col = wn * 64 + u * 8 + (lane & 3) * 2;
            const float b0 = bias[n0 + col], b1 = bias[n0 + col + 1];
            half_t* p = KVo + (size_t)row * 512 + cb + col;
            *(__half2*)p             = __floats2half2_rn(c[t][u][0] + b0, c[t][u][1] + b1);
            *(__half2*)(p + 8 * 512) = __floats2half2_rn(c[t][u][2] + b0, c[t][u][3] + b1);
        }
}

// attention body: one warp per face, half2 math, butterfly multi-reduce
__device__ __forceinline__ void attn_body(int face, const int* __restrict__ loop,
                                          const half_t* __restrict__ Q,
                                          const half_t* __restrict__ KV,
                                          half_t* __restrict__ attc,
                                          int* sidx /* [16] this warp */)
{
    const int lane = threadIdx.x & 31;
    if (lane < 16) sidx[lane] = loop[face * MAXLOOP + lane];
    __syncwarp();

    bool v = false;
    if (lane < 16) {
        const int my = sidx[lane];
        v = (my >= 0);
        for (int j = 0; v && j < lane; ++j)
            if (sidx[j] == my) v = false;
    }
    const unsigned bal = __ballot_sync(0xffffffffu, v);

    const int safe = sidx[0];
    int eidx[16];
#pragma unroll
    for (int i = 0; i < 16; ++i) {
        const int ii = sidx[i];
        eidx[i] = (bal & (1u << i)) ? ii : safe;
    }

    const __half2 scale2 = __float2half2_rn(0.08838834764831845f);  // 1/sqrt(128)
    uint4 qr = *(const uint4*)(Q + (size_t)face * EDIM + lane * 8);
    const __half2 q0 = __hmul2(u2h(qr.x), scale2);
    const __half2 q1 = __hmul2(u2h(qr.y), scale2);
    const __half2 q2 = __hmul2(u2h(qr.z), scale2);
    const __half2 q3 = __hmul2(u2h(qr.w), scale2);

    float p[16];
#pragma unroll
    for (int i = 0; i < 16; ++i) {
        uint4 kr = *(const uint4*)(KV + (size_t)eidx[i] * 512 + lane * 8);
        __half2 acc = __hmul2(q0, u2h(kr.x));
        acc = __hfma2(q1, u2h(kr.y), acc);
        acc = __hfma2(q2, u2h(kr.z), acc);
        acc = __hfma2(q3, u2h(kr.w), acc);
        const float2 f = __half22float2(acc);
        p[i] = f.x + f.y;
    }
#pragma unroll
    for (int d = 8; d >= 1; d >>= 1) {
#pragma unroll
        for (int i = 0; i < d; ++i) {
            const float lo = p[i], hi = p[i + d];
            const float x = (lane & d) ? lo : hi;
            const float y = __shfl_xor_sync(0xffffffffu, x, d);
            p[i] = ((lane & d) ? hi : lo) + y;
        }
    }

    const bool mv = (bal >> (lane & 15)) & 1u;
    float s = mv ? p[0] : -3e38f;
    float mx = s;
#pragma unroll
    for (int d = 8; d; d >>= 1) mx = fmaxf(mx, __shfl_xor_sync(0xffffffffu, mx, d));
    const float e = mv ? __expf(s - mx) : 0.f;
    float sum = e;
#pragma unroll
    for (int d = 8; d; d >>= 1) sum += __shfl_xor_sync(0xffffffffu, sum, d);
    const float w = e / sum;

    __half2 a0 = __float2half2_rn(0.f), a1 = a0, a2 = a0, a3 = a0;
    const int hb = lane & 16;
#pragma unroll
    for (int i = 0; i < 16; ++i) {
        const float wi = __shfl_sync(0xffffffffu, w, hb | i);
        const __half2 w2 = __float2half2_rn(wi);
        uint4 vr = *(const uint4*)(KV + (size_t)eidx[i] * 512 + 256 + lane * 8);
        a0 = __hfma2(w2, u2h(vr.x), a0);
        a1 = __hfma2(w2, u2h(vr.y), a1);
        a2 = __hfma2(w2, u2h(vr.z), a2);
        a3 = __hfma2(w2, u2h(vr.w), a3);
    }
    *(uint4*)&attc[(size_t)face * 256 + lane * 8] =
        make_uint4(h2u(a0), h2u(a1), h2u(a2), h2u(a3));
}

// ---------------------------------------------------------------------------
// QKV GEMM (layer 1): grid = 64 mtiles x 6 ntiles. ntile<2 -> Q fp16 (A=acts);
// ntile>=2 -> K/V fp16 (A=edges). CTA 128x128, 256 threads.
// ---------------------------------------------------------------------------
#define SMEM_QKV (2 * ((128 + 128) * 144))

__global__ __launch_bounds__(256, 2)
void qkv_mma(const half_t* __restrict__ Ain, const half_t* __restrict__ Ein,
             const half_t* __restrict__ W, const float* __restrict__ bias,
             half_t* __restrict__ Qo, half_t* __restrict__ KVo)
{
    extern __shared__ char smem[];
    const u32 sb = smem_u32(smem);
    const int mtile = blockIdx.x & 63, ntile = blockIdx.x >> 6;
    const int m0 = mtile * 128, n0 = ntile * 128;
    const half_t* A = (ntile < 2) ? Ain : Ein;
    const half_t* B = W + (size_t)n0 * 256;
    const int wid = threadIdx.x >> 5, lane = threadIdx.x & 31;
    const int wm = wid >> 1, wn = wid & 1;

    constexpr u32 CHUNK = (128 + 128) * 144u;
    float c[2][8][4] = {};
    load_chunk<128, 128, 256>(sb, A, B, m0, 0);         CP_COMMIT();
    load_chunk<128, 128, 256>(sb + CHUNK, A, B, m0, 1); CP_COMMIT();
#pragma unroll
    for (int kc = 0; kc < 4; ++kc) {
        if (kc < 3) { CP_WAIT(1); } else { CP_WAIT(0); }
        __syncthreads();
        const u32 base = sb + (kc & 1) * CHUNK;
        mma_chunk(base, base + 128 * 144u, wm, wn, lane, c);
        __syncthreads();
        if (kc < 2) {
            load_chunk<128, 128, 256>(sb + (kc & 1) * CHUNK, A, B, m0, kc + 2);
            CP_COMMIT();
        }
    }

    half_t* C; int ldc, cb;
    if (ntile < 2) { C = Qo;  ldc = 256; cb = n0; }
    else           { C = KVo; ldc = 512; cb = n0 - 256; }
#pragma unroll
    for (int t = 0; t < 2; ++t)
#pragma unroll
        for (int u = 0; u < 8; ++u) {
            const int row = m0 + wm * 32 + t * 16 + (lane >> 2);
            const int col = wn * 64 + u * 8 + (lane & 3) * 2;
            const float b0 = bias[n0 + col], b1 = bias[n0 + col + 1];
            half_t* p = C + (size_t)row * ldc + cb + col;
            *(__half2*)p             = __floats2half2_rn(c[t][u][0] + b0, c[t][u][1] + b1);
            *(__half2*)(p + 8 * ldc) = __floats2half2_rn(c[t][u][2] + b0, c[t][u][3] + b1);
        }
}

// ---------------------------------------------------------------------------
// Fat launch: blocks [0,256) compute layer-2 K/V GEMM; blocks [256,1280)
// run layer-1 attention. Complementary pipes -> concurrent execution.
// ---------------------------------------------------------------------------
__global__ __launch_bounds__(256)
void attn_kv2(const int* __restrict__ loop, const half_t* __restrict__ Q,
              const half_t* __restrict__ KV, half_t* __restrict__ attc,
              const half_t* __restrict__ Ec, const half_t* __restrict__ W2,
              const float* __restrict__ bias2, half_t* __restrict__ KV2o)
{
    extern __shared__ char smem[];
    if (blockIdx.x < 256) {
        const int m0 = (blockIdx.x & 63) * 128;
        const int n0 = 256 + (blockIdx.x >> 6) * 128;   // K/V ntiles only
        kv_gemm_body(smem_u32(smem), Ec, W2, bias2, m0, n0, KV2o);
    } else {
        __shared__ int sidx[8][16];
        const int warp = threadIdx.x >> 5;
        const int face = ((blockIdx.x - 256) << 3) + warp;
        attn_body(face, loop, Q, KV, attc, sidx[warp]);
    }
}

// plain attention launch (layer 2)
__global__ __launch_bounds__(256)
void attn_kernel(const int* __restrict__ loop, const half_t* __restrict__ Q,
                 const half_t* __restrict__ KV, half_t* __restrict__ attc)
{
    __shared__ int sidx[8][16];
    const int warp = threadIdx.x >> 5;
    const int face = (blockIdx.x << 3) + warp;
    attn_body(face, loop, Q, KV, attc, sidx[warp]);
}

// ---------------------------------------------------------------------------
// Out-proj GEMM + bias + residual + LayerNorm (+ optional fused next-layer
// Q GEMM: Q2 = LN_out @ Wq2^T + bq2, using smem-resident fp16 X tile).
// CTA 64x256 (full row), grid 128, 256 threads, warps 2x4.
// smem: [0, 92160) stage-1 pipe (aliased by fp32 stash after),
//       [92160, 129024) fp16 X tile (4 chunks x 64 x 144B),
//       [129024, 202752) stage-2 B double buffer (2 x 256 x 144B).
// ---------------------------------------------------------------------------
#define SMEM_OUT   202752
#define OFF_XA     92160u
#define OFF_B2     129024u
#define XA_CHUNK   (64u * 144u)       // 9216
#define B2_CHUNK   (256u * 144u)      // 36864

__global__ __launch_bounds__(256, 1)
void outln_mma(const half_t* __restrict__ A, const half_t* __restrict__ W,
               const float* __restrict__ bias, const float* __restrict__ resid,
               const float* __restrict__ gg, const float* __restrict__ bb,
               float* __restrict__ out,
               const half_t* __restrict__ Wq2, const float* __restrict__ bq2,
               half_t* __restrict__ Q2o)
{
    extern __shared__ char smem[];
    const u32 sb = smem_u32(smem);
    const int m0 = blockIdx.x * 64;
    const int wid = threadIdx.x >> 5, lane = threadIdx.x & 31;
    const int wm = wid & 1, wn = wid >> 1;

    constexpr u32 CHUNK = (64 + 256) * 144u;
    float c[2][8][4] = {};
    load_chunk<64, 256, 256>(sb, A, W, m0, 0);         CP_COMMIT();
    load_chunk<64, 256, 256>(sb + CHUNK, A, W, m0, 1); CP_COMMIT();
#pragma unroll
    for (int kc = 0; kc < 4; ++kc) {
        if (kc < 3) { CP_WAIT(1); } else { CP_WAIT(0); }
        __syncthreads();
        const u32 base = sb + (kc & 1) * CHUNK;
        mma_chunk(base, base + 64 * 144u, wm, wn, lane, c);
        __syncthreads();
        if (kc < 2) {
            load_chunk<64, 256, 256>(sb + (kc & 1) * CHUNK, A, W, m0, kc + 2);
            CP_COMMIT();
        }
    }

    // prefetch stage-2 B chunks 0/1 (disjoint smem region; hides under epilogue)
    if (Wq2) {
        load_b256<256>(sb + OFF_B2,            Wq2, 0); CP_COMMIT();
        load_b256<256>(sb + OFF_B2 + B2_CHUNK, Wq2, 1); CP_COMMIT();
    }

    // stash: 64 rows x 264 fp32 (aliases stage-1 pipe — all reads done)
    float* stash = (float*)smem;
#pragma unroll
    for (int t = 0; t < 2; ++t)
#pragma unroll
        for (int u = 0; u < 8; ++u) {
            const int r = wm * 32 + t * 16 + (lane >> 2);
            const int col = wn * 64 + u * 8 + (lane & 3) * 2;
            const float b0 = bias[col], b1 = bias[col + 1];
            *(float2*)&stash[(size_t)r * 264 + col] =
                make_float2(c[t][u][0] + b0, c[t][u][1] + b1);
            *(float2*)&stash[(size_t)(r + 8) * 264 + col] =
                make_float2(c[t][u][2] + b0, c[t][u][3] + b1);
        }
    __syncthreads();

#pragma unroll
    for (int i = 0; i < 8; ++i) {
        const int r = wid * 8 + i;          // 0..63
        const int grow = m0 + r;
        const int c0 = lane * 8;
        float4 s0 = *(const float4*)&stash[(size_t)r * 264 + c0];
        float4 s1 = *(const float4*)&stash[(size_t)r * 264 + c0 + 4];
        const float* rp = resid + (size_t)grow * EDIM + c0;
        float4 r0 = *(const float4*)rp, r1 = *(const float4*)(rp + 4);
        float v[8] = { s0.x + r0.x, s0.y + r0.y, s0.z + r0.z, s0.w + r0.w,
                       s1.x + r1.x, s1.y + r1.y, s1.z + r1.z, s1.w + r1.w };
        float s = 0.f, ss = 0.f;
#pragma unroll
        for (int j = 0; j < 8; ++j) { s += v[j]; ss += v[j] * v[j]; }
#pragma unroll
        for (int d = 16; d; d >>= 1) {
            s  += __shfl_xor_sync(0xffffffffu, s,  d);
            ss += __shfl_xor_sync(0xffffffffu, ss, d);
        }
        const float m   = s * (1.f / 256.f);
        const float var = ss * (1.f / 256.f) - m * m;
        const float inv = rsqrtf(var + 1e-5f);

        float4 g0 = *(const float4*)(gg + c0), g1 = *(const float4*)(gg + c0 + 4);
        float4 b0 = *(const float4*)(bb + c0), b1 = *(const float4*)(bb + c0 + 4);
        float o[8];
        o[0] = (v[0] - m) * inv * g0.x + b0.x; o[1] = (v[1] - m) * inv * g0.y + b0.y;
        o[2] = (v[2] - m) * inv * g0.z + b0.z; o[3] = (v[3] - m) * inv * g0.w + b0.w;
        o[4] = (v[4] - m) * inv * g1.x + b1.x; o[5] = (v[5] - m) * inv * g1.y + b1.y;
        o[6] = (v[6] - m) * inv * g1.z + b1.z; o[7] = (v[7] - m) * inv * g1.w + b1.w;

        float* op = out + (size_t)grow * EDIM + c0;
        *(float4*)op       = make_float4(o[0], o[1], o[2], o[3]);
        *(float4*)(op + 4) = make_float4(o[4], o[5], o[6], o[7]);

        if (Wq2) {
            const uint4 hx = round8h(make_float4(o[0], o[1], o[2], o[3]),
                                     make_float4(o[4], o[5], o[6], o[7]));
            // store fp16 X into smem A-layout: chunk (c0/64), col (c0%64)
            const u32 xa = sb + OFF_XA + (u32)(c0 >> 6) * XA_CHUNK
                         + (u32)r * 144u + (u32)(c0 & 63) * 2u;
            asm volatile("st.shared.v4.b32 [%0], {%1, %2, %3, %4};"
                         :: "r"(xa), "r"(hx.x), "r"(hx.y), "r"(hx.z), "r"(hx.w)
                         : "memory");
        }
    }

    if (!Wq2) return;

    // ---- stage 2: Q2 = X @ Wq2^T + bq2 (A resident in smem, B pipelined) ----
    float c2[2][8][4] = {};
#pragma unroll
    for (int kc = 0; kc < 4; ++kc) {
        if (kc < 3) { CP_WAIT(1); } else { CP_WAIT(0); }
        __syncthreads();   // also orders XA writes before first mma
        mma_chunk(sb + OFF_XA + kc * XA_CHUNK,
                  sb + OFF_B2 + (kc & 1) * B2_CHUNK, wm, wn, lane, c2);
        __syncthreads();
        if (kc < 2) {
            load_b256<256>(sb + OFF_B2 + (kc & 1) * B2_CHUNK, Wq2, kc + 2);
            CP_COMMIT();
        }
    }
#pragma unroll
    for (int t = 0; t < 2; ++t)
#pragma unroll
        for (int u = 0; u < 8; ++u) {
            const int row = m0 + wm * 32 + t * 16 + (lane >> 2);
            const int col = wn * 64 + u * 8 + (lane & 3) * 2;
            const float b0 = bq2[col], b1 = bq2[col + 1];
            half_t* p = Q2o + (size_t)row * 256 + col;
            *(__half2*)p             = __floats2half2_rn(c2[t][u][0] + b0, c2[t][u][1] + b1);
            *(__half2*)(p + 8 * 256) = __floats2half2_rn(c2[t][u][2] + b0, c2[t][u][3] + b1);
        }
}

// ---------------------------------------------------------------------------
extern "C" void kernel_launch(void* const* d_in, const int* in_sizes, int n_in,
                              void* d_out, int out_size)
{
    const int*   loop  = (const int*)  d_in[0];
    const float* edge  = (const float*)d_in[2];
    const float* face  = (const float*)d_in[3];
    const float* w_in1  = (const float*)d_in[4];
    const float* b_in1  = (const float*)d_in[5];
    const float* w_out1 = (const float*)d_in[6];
    const float* b_out1 = (const float*)d_in[7];
    const float* ln1_g  = (const float*)d_in[8];
    const float* ln1_b  = (const float*)d_in[9];
    const float* w_in2  = (const float*)d_in[10];
    const float* b_in2  = (const float*)d_in[11];
    const float* w_out2 = (const float*)d_in[12];
    const float* b_out2 = (const float*)d_in[13];
    const float* ln2_g  = (const float*)d_in[14];
    const float* ln2_b  = (const float*)d_in[15];

    float *X;
    half_t *Q, *KV, *KV2, *Ac, *Ec, *ATTc, *Wc1, *Wc2, *Wo1, *Wo2;
    cudaGetSymbolAddress((void**)&Q,    g_Q);
    cudaGetSymbolAddress((void**)&KV,   g_KV);
    cudaGetSymbolAddress((void**)&KV2,  g_KV2);
    cudaGetSymbolAddress((void**)&X,    g_X);
    cudaGetSymbolAddress((void**)&Ac,   g_Ac);
    cudaGetSymbolAddress((void**)&Ec,   g_Ec);
    cudaGetSymbolAddress((void**)&ATTc, g_ATTc);
    cudaGetSymbolAddress((void**)&Wc1,  g_Wc1);
    cudaGetSymbolAddress((void**)&Wc2,  g_Wc2);
    cudaGetSymbolAddress((void**)&Wo1,  g_Wo1);
    cudaGetSymbolAddress((void**)&Wo2,  g_Wo2);

    cudaFuncSetAttribute(qkv_mma,   cudaFuncAttributeMaxDynamicSharedMemorySize, SMEM_QKV);
    cudaFuncSetAttribute(attn_kv2,  cudaFuncAttributeMaxDynamicSharedMemorySize, SMEM_QKV);
    cudaFuncSetAttribute(outln_mma, cudaFuncAttributeMaxDynamicSharedMemorySize, SMEM_OUT);

    conv_all<<<2304, 256>>>(face, edge, w_in1, w_out1, w_in2, w_out2,
                            Ac, Ec, Wc1, Wo1, Wc2, Wo2);

    // ---- layer 1 (+ overlapped layer-2 K/V GEMM) ----
    qkv_mma  <<<384, 256, SMEM_QKV>>>(Ac, Ec, Wc1, b_in1, Q, KV);
    attn_kv2 <<<1280, 256, SMEM_QKV>>>(loop, Q, KV, ATTc, Ec, Wc2, b_in2, KV2);
    outln_mma<<<128, 256, SMEM_OUT>>>(ATTc, Wo1, b_out1, face, ln1_g, ln1_b, X,
                                      Wc2, b_in2, Q);   // fused Q2 = X @ Wq2^T

    // ---- layer 2 ----
    attn_kernel<<<1024, 256>>>(loop, Q, KV2, ATTc);
    outln_mma<<<128, 256, SMEM_OUT>>>(ATTc, Wo2, b_out2, X, ln2_g, ln2_b,
                                      (float*)d_out,
                                      (const half_t*)nullptr, (const float*)nullptr,
                                      (half_t*)nullptr);
}

// round 15
// speedup vs baseline: 1.0640x; 1.0640x over previous
#include <cuda_runtime.h>
#include <cuda_fp16.h>
#include <cstdint>

typedef unsigned int u32;
typedef __half half_t;

#define EDIM    256
#define MAXLOOP 16

// ---------------------------------------------------------------------------
// Global scratch (no allocation allowed)
// ---------------------------------------------------------------------------
__device__ half_t g_Q  [8192 * 256];       // fp16 Q
__device__ half_t g_KV [8192 * 512];       // fp16: K cols 0..255, V cols 256..511
__device__ float  g_X  [8192 * 256];
__device__ half_t g_Ac [8192 * 256];       // activations fp16 (face, then X)
__device__ half_t g_Ec [8192 * 256];       // edges fp16
__device__ half_t g_ATTc[8192 * 256];      // attention out fp16
__device__ half_t g_Wc1[768 * 256];        // weights fp16
__device__ half_t g_Wc2[768 * 256];
__device__ half_t g_Wo1[256 * 256];
__device__ half_t g_Wo2[256 * 256];

// ---------------------------------------------------------------------------
// Helpers (plain sm_80+ features only — harness lowers to compute_103 PTX)
// ---------------------------------------------------------------------------
__device__ __forceinline__ u32 smem_u32(const void* p) {
    u32 a; asm("{ .reg .u64 t; cvta.to.shared.u64 t, %1; cvt.u32.u64 %0, t; }"
               : "=r"(a) : "l"(p));
    return a;
}
__device__ __forceinline__ void cpa16(u32 d, const void* s) {
    asm volatile("cp.async.ca.shared.global [%0], [%1], 16;" :: "r"(d), "l"(s));
}
#define CP_COMMIT() asm volatile("cp.async.commit_group;" ::: "memory")
#define CP_WAIT(n)  asm volatile("cp.async.wait_group %0;" :: "n"(n) : "memory")
#define LDSM4(r0, r1, r2, r3, a) \
    asm volatile("ldmatrix.sync.aligned.m8n8.x4.shared.b16 {%0,%1,%2,%3}, [%4];" \
                 : "=r"(r0), "=r"(r1), "=r"(r2), "=r"(r3) : "r"(a))

__device__ __forceinline__ void mma_f16(float* d, const u32* a, const u32* b) {
    asm volatile("mma.sync.aligned.m16n8k16.row.col.f32.f16.f16.f32 "
                 "{%0,%1,%2,%3}, {%4,%5,%6,%7}, {%8,%9}, {%0,%1,%2,%3};"
                 : "+f"(d[0]), "+f"(d[1]), "+f"(d[2]), "+f"(d[3])
                 : "r"(a[0]), "r"(a[1]), "r"(a[2]), "r"(a[3]),
                   "r"(b[0]), "r"(b[1]));
}

__device__ __forceinline__ u32 h2u(__half2 h) { return *reinterpret_cast<u32*>(&h); }
__device__ __forceinline__ __half2 u2h(u32 u) { return *reinterpret_cast<__half2*>(&u); }

// round 8 fp32 -> 8 fp16 (uint4)
__device__ __forceinline__ uint4 round8h(float4 f0, float4 f1) {
    return make_uint4(h2u(__floats2half2_rn(f0.x, f0.y)),
                      h2u(__floats2half2_rn(f0.z, f0.w)),
                      h2u(__floats2half2_rn(f1.x, f1.y)),
                      h2u(__floats2half2_rn(f1.z, f1.w)));
}

// ---------------------------------------------------------------------------
// conv_all: face[8192], edge[8192], w1[768], o1[256], w2[768], o2[256]
// fp32 [rows][256] -> fp16 [rows][256], one launch (18432 rows, 2304 blocks)
// ---------------------------------------------------------------------------
__global__ void conv_all(const float* __restrict__ f, const float* __restrict__ e,
                         const float* __restrict__ w1, const float* __restrict__ o1,
                         const float* __restrict__ w2, const float* __restrict__ o2,
                         half_t* __restrict__ Ac, half_t* __restrict__ Ec,
                         half_t* __restrict__ W1, half_t* __restrict__ O1,
                         half_t* __restrict__ W2, half_t* __restrict__ O2)
{
    const int idx = blockIdx.x * 256 + threadIdx.x;
    int row = idx >> 5;
    const int c = (idx & 31) * 8;
    const float* src; half_t* dst;
    if      (row < 8192)  { src = f;  dst = Ac; }
    else if (row < 16384) { src = e;  dst = Ec; row -= 8192; }
    else if (row < 17152) { src = w1; dst = W1; row -= 16384; }
    else if (row < 17408) { src = o1; dst = O1; row -= 17152; }
    else if (row < 18176) { src = w2; dst = W2; row -= 17408; }
    else                  { src = o2; dst = O2; row -= 18176; }
    const float* s = src + (size_t)row * 256 + c;
    float4 f0 = *(const float4*)s, f1 = *(const float4*)(s + 4);
    *(uint4*)&dst[(size_t)row * 256 + c] = round8h(f0, f1);
}

// ---------------------------------------------------------------------------
// GEMM loaders (K-chunk 64, 144B padded rows)
// ---------------------------------------------------------------------------
template<int MB, int NB, int NTH>
__device__ __forceinline__ void load_chunk(u32 sb, const half_t* __restrict__ A,
                                           const half_t* __restrict__ B, int m0, int kc)
{
    const int tid = threadIdx.x;
    constexpr u32 AREG = MB * 144u;
#pragma unroll
    for (int i = tid; i < MB * 8; i += NTH) {
        const int r = i >> 3, s = i & 7;
        cpa16(sb + r * 144 + s * 16,
              A + ((size_t)(m0 + r) << 8) + kc * 64 + s * 8);
    }
#pragma unroll
    for (int i = tid; i < NB * 8; i += NTH) {
        const int r = i >> 3, s = i & 7;
        cpa16(sb + AREG + r * 144 + s * 16,
              B + ((size_t)r << 8) + kc * 64 + s * 8);
    }
}

// warp tile 32x64
template<int MB, int NB>
__device__ __forceinline__ void mma_chunk(u32 sb, int wm, int wn, int lane,
                                          float c[2][8][4])
{
    constexpr u32 OFF_B = MB * 144u;
    const u32 arow  = lane & 15;
    const u32 ahalf = (lane >> 4) * 16;
#pragma unroll
    for (int ks = 0; ks < 4; ++ks) {
        const u32 kb = ks * 32 + ahalf;
        u32 ah[2][4];
#pragma unroll
        for (int t = 0; t < 2; ++t) {
            const u32 ad = sb + (wm * 32 + t * 16 + arow) * 144 + kb;
            LDSM4(ah[t][0], ah[t][1], ah[t][2], ah[t][3], ad);
        }
#pragma unroll
        for (int p = 0; p < 4; ++p) {
            const u32 bd = sb + OFF_B + (wn * 64 + p * 16 + arow) * 144 + kb;
            u32 m0r, m1r, m2r, m3r;
            LDSM4(m0r, m1r, m2r, m3r, bd);
            u32 b0[2] = { m0r, m2r }, b1[2] = { m1r, m3r };
#pragma unroll
            for (int t = 0; t < 2; ++t) {
                mma_f16(c[t][2 * p],     ah[t], b0);
                mma_f16(c[t][2 * p + 1], ah[t], b1);
            }
        }
    }
}

// ---------------------------------------------------------------------------
// QKV GEMM: grid = 64 mtiles x 6 ntiles. ntile<2 -> Q fp16 (A=acts);
// ntile>=2 -> K/V fp16 (A=edges). CTA 128x128, 256 threads, K64 2-stage.
// ---------------------------------------------------------------------------
#define SMEM_QKV (2 * ((128 + 128) * 144))

__global__ __launch_bounds__(256, 2)
void qkv_mma(const half_t* __restrict__ Ain, const half_t* __restrict__ Ein,
             const half_t* __restrict__ W, const float* __restrict__ bias,
             half_t* __restrict__ Qo, half_t* __restrict__ KVo)
{
    extern __shared__ char smem[];
    const u32 sb = smem_u32(smem);
    const int mtile = blockIdx.x & 63, ntile = blockIdx.x >> 6;
    const int m0 = mtile * 128, n0 = ntile * 128;
    const half_t* A = (ntile < 2) ? Ain : Ein;
    const half_t* B = W + (size_t)n0 * 256;
    const int wid = threadIdx.x >> 5, lane = threadIdx.x & 31;
    const int wm = wid >> 1, wn = wid & 1;

    constexpr u32 CHUNK = (128 + 128) * 144u;
    float c[2][8][4] = {};
    load_chunk<128, 128, 256>(sb, A, B, m0, 0);         CP_COMMIT();
    load_chunk<128, 128, 256>(sb + CHUNK, A, B, m0, 1); CP_COMMIT();
#pragma unroll
    for (int kc = 0; kc < 4; ++kc) {
        if (kc < 3) { CP_WAIT(1); } else { CP_WAIT(0); }
        __syncthreads();
        mma_chunk<128, 128>(sb + (kc & 1) * CHUNK, wm, wn, lane, c);
        __syncthreads();
        if (kc < 2) {
            load_chunk<128, 128, 256>(sb + (kc & 1) * CHUNK, A, B, m0, kc + 2);
            CP_COMMIT();
        }
    }

    half_t* C; int ldc, cb;
    if (ntile < 2) { C = Qo;  ldc = 256; cb = n0; }
    else           { C = KVo; ldc = 512; cb = n0 - 256; }
#pragma unroll
    for (int t = 0; t < 2; ++t)
#pragma unroll
        for (int u = 0; u < 8; ++u) {
            const int row = m0 + wm * 32 + t * 16 + (lane >> 2);
            const int col = wn * 64 + u * 8 + (lane & 3) * 2;
            const float b0 = bias[n0 + col], b1 = bias[n0 + col + 1];
            half_t* p = C + (size_t)row * ldc + cb + col;
            *(__half2*)p             = __floats2half2_rn(c[t][u][0] + b0, c[t][u][1] + b1);
            *(__half2*)(p + 8 * ldc) = __floats2half2_rn(c[t][u][2] + b0, c[t][u][3] + b1);
        }
}

// ---------------------------------------------------------------------------
// Out-proj GEMM + bias + residual + LayerNorm (round-6 proven config).
// CTA 64x256 (full row), grid 128, 256 threads, warps 2x4 (tile 32x64).
// ---------------------------------------------------------------------------
#define SMEM_OUT (2 * ((64 + 256) * 144))

__global__ __launch_bounds__(256, 2)
void outln_mma(const half_t* __restrict__ A, const half_t* __restrict__ W,
               const float* __restrict__ bias, const float* __restrict__ resid,
               const float* __restrict__ gg, const float* __restrict__ bb,
               float* __restrict__ out, half_t* __restrict__ xc)
{
    extern __shared__ char smem[];
    const u32 sb = smem_u32(smem);
    const int m0 = blockIdx.x * 64;
    const int wid = threadIdx.x >> 5, lane = threadIdx.x & 31;
    const int wm = wid & 1, wn = wid >> 1;

    constexpr u32 CHUNK = (64 + 256) * 144u;
    float c[2][8][4] = {};
    load_chunk<64, 256, 256>(sb, A, W, m0, 0);         CP_COMMIT();
    load_chunk<64, 256, 256>(sb + CHUNK, A, W, m0, 1); CP_COMMIT();
#pragma unroll
    for (int kc = 0; kc < 4; ++kc) {
        if (kc < 3) { CP_WAIT(1); } else { CP_WAIT(0); }
        __syncthreads();
        mma_chunk<64, 256>(sb + (kc & 1) * CHUNK, wm, wn, lane, c);
        __syncthreads();
        if (kc < 2) {
            load_chunk<64, 256, 256>(sb + (kc & 1) * CHUNK, A, W, m0, kc + 2);
            CP_COMMIT();
        }
    }

    // stash: 64 rows x 264 floats (aliases pipe buffers — all reads done)
    float* stash = (float*)smem;
#pragma unroll
    for (int t = 0; t < 2; ++t)
#pragma unroll
        for (int u = 0; u < 8; ++u) {
            const int r = wm * 32 + t * 16 + (lane >> 2);
            const int col = wn * 64 + u * 8 + (lane & 3) * 2;
            const float b0 = bias[col], b1 = bias[col + 1];
            *(float2*)&stash[(size_t)r * 264 + col] =
                make_float2(c[t][u][0] + b0, c[t][u][1] + b1);
            *(float2*)&stash[(size_t)(r + 8) * 264 + col] =
                make_float2(c[t][u][2] + b0, c[t][u][3] + b1);
        }
    __syncthreads();

#pragma unroll
    for (int i = 0; i < 8; ++i) {
        const int r = wid * 8 + i;          // 0..63
        const int grow = m0 + r;
        const int c0 = lane * 8;
        float4 s0 = *(const float4*)&stash[(size_t)r * 264 + c0];
        float4 s1 = *(const float4*)&stash[(size_t)r * 264 + c0 + 4];
        const float* rp = resid + (size_t)grow * EDIM + c0;
        float4 r0 = *(const float4*)rp, r1 = *(const float4*)(rp + 4);
        float v[8] = { s0.x + r0.x, s0.y + r0.y, s0.z + r0.z, s0.w + r0.w,
                       s1.x + r1.x, s1.y + r1.y, s1.z + r1.z, s1.w + r1.w };
        float s = 0.f, ss = 0.f;
#pragma unroll
        for (int j = 0; j < 8; ++j) { s += v[j]; ss += v[j] * v[j]; }
#pragma unroll
        for (int d = 16; d; d >>= 1) {
            s  += __shfl_xor_sync(0xffffffffu, s,  d);
            ss += __shfl_xor_sync(0xffffffffu, ss, d);
        }
        const float m   = s * (1.f / 256.f);
        const float var = ss * (1.f / 256.f) - m * m;
        const float inv = rsqrtf(var + 1e-5f);

        float4 g0 = *(const float4*)(gg + c0), g1 = *(const float4*)(gg + c0 + 4);
        float4 b0 = *(const float4*)(bb + c0), b1 = *(const float4*)(bb + c0 + 4);
        float o[8];
        o[0] = (v[0] - m) * inv * g0.x + b0.x; o[1] = (v[1] - m) * inv * g0.y + b0.y;
        o[2] = (v[2] - m) * inv * g0.z + b0.z; o[3] = (v[3] - m) * inv * g0.w + b0.w;
        o[4] = (v[4] - m) * inv * g1.x + b1.x; o[5] = (v[5] - m) * inv * g1.y + b1.y;
        o[6] = (v[6] - m) * inv * g1.z + b1.z; o[7] = (v[7] - m) * inv * g1.w + b1.w;

        float* op = out + (size_t)grow * EDIM + c0;
        *(float4*)op       = make_float4(o[0], o[1], o[2], o[3]);
        *(float4*)(op + 4) = make_float4(o[4], o[5], o[6], o[7]);

        if (xc) {
            *(uint4*)&xc[(size_t)grow * 256 + c0] =
                round8h(make_float4(o[0], o[1], o[2], o[3]),
                        make_float4(o[4], o[5], o[6], o[7]));
        }
    }
}

// ---------------------------------------------------------------------------
// Attention: one warp per face, COMPACTED valid-edge list (skips invalid/dup
// slot loads -> ~25-30% less L2 gather traffic), half2 math, butterfly
// multi-reduce, fp32 softmax.
// ---------------------------------------------------------------------------
__global__ __launch_bounds__(256)
void attn_kernel(const int* __restrict__ loop, const half_t* __restrict__ Q,
                 const half_t* __restrict__ KV, half_t* __restrict__ attc)
{
    const int warp = threadIdx.x >> 5;
    const int lane = threadIdx.x & 31;
    const int face = (blockIdx.x << 3) + warp;

    __shared__ int sidx[8][16];
    __shared__ int cidx[8][16];
    if (lane < 16) sidx[warp][lane] = loop[face * MAXLOOP + lane];
    __syncwarp();

    // validity + dedup (keep first occurrence; -1/-2 invalid)
    bool v = false;
    int my = 0;
    if (lane < 16) {
        my = sidx[warp][lane];
        v = (my >= 0);
        for (int j = 0; v && j < lane; ++j)
            if (sidx[warp][j] == my) v = false;
    }
    const unsigned bal = __ballot_sync(0xffffffffu, v);
    const int nv = __popc(bal & 0xffffu);          // >=1 (slot 0 always valid)

    // compact valid indices: valid lane i -> position popc(bal & ((1<<i)-1))
    if (v) cidx[warp][__popc(bal & ((1u << lane) - 1u))] = my;
    __syncwarp();

    const __half2 scale2 = __float2half2_rn(0.08838834764831845f);  // 1/sqrt(128)
    uint4 qr = *(const uint4*)(Q + (size_t)face * EDIM + lane * 8);
    const __half2 q0 = __hmul2(u2h(qr.x), scale2);
    const __half2 q1 = __hmul2(u2h(qr.y), scale2);
    const __half2 q2 = __hmul2(u2h(qr.z), scale2);
    const __half2 q3 = __hmul2(u2h(qr.w), scale2);

    // partial dots for the nv compacted edges (predicate is warp-uniform ->
    // loads stay independent + pipelined, dead slots issue NO traffic)
    float p[16];
#pragma unroll
    for (int i = 0; i < 16; ++i) {
        p[i] = 0.f;
        if (i < nv) {
            uint4 kr = *(const uint4*)(KV + (size_t)cidx[warp][i] * 512 + lane * 8);
            __half2 acc = __hmul2(q0, u2h(kr.x));
            acc = __hfma2(q1, u2h(kr.y), acc);
            acc = __hfma2(q2, u2h(kr.z), acc);
            acc = __hfma2(q3, u2h(kr.w), acc);
            const float2 f = __half22float2(acc);
            p[i] = f.x + f.y;
        }
    }

    // butterfly multi-reduce: lane L ends with compact-slot (L&15)'s score
    // for head (L>>4). Slots >= nv carry garbage zeros, masked below.
#pragma unroll
    for (int d = 8; d >= 1; d >>= 1) {
#pragma unroll
        for (int i = 0; i < d; ++i) {
            const float lo = p[i], hi = p[i + d];
            const float x = (lane & d) ? lo : hi;
            const float y = __shfl_xor_sync(0xffffffffu, x, d);
            p[i] = ((lane & d) ? hi : lo) + y;
        }
    }

    const bool mv = (lane & 15) < nv;
    float s = mv ? p[0] : -3e38f;
    float mx = s;
#pragma unroll
    for (int d = 8; d; d >>= 1) mx = fmaxf(mx, __shfl_xor_sync(0xffffffffu, mx, d));
    const float e = mv ? __expf(s - mx) : 0.f;
    float sum = e;
#pragma unroll
    for (int d = 8; d; d >>= 1) sum += __shfl_xor_sync(0xffffffffu, sum, d);
    const float w = e / sum;

    // V accumulation over compacted edges only
    __half2 a0 = __float2half2_rn(0.f), a1 = a0, a2 = a0, a3 = a0;
    const int hb = lane & 16;
#pragma unroll
    for (int i = 0; i < 16; ++i) {
        if (i < nv) {
            const float wi = __shfl_sync(0xffffffffu, w, hb | i);
            const __half2 w2 = __float2half2_rn(wi);
            uint4 vr = *(const uint4*)(KV + (size_t)cidx[warp][i] * 512 + 256 + lane * 8);
            a0 = __hfma2(w2, u2h(vr.x), a0);
            a1 = __hfma2(w2, u2h(vr.y), a1);
            a2 = __hfma2(w2, u2h(vr.z), a2);
            a3 = __hfma2(w2, u2h(vr.w), a3);
        }
    }
    *(uint4*)&attc[(size_t)face * 256 + lane * 8] =
        make_uint4(h2u(a0), h2u(a1), h2u(a2), h2u(a3));
}

// ---------------------------------------------------------------------------
extern "C" void kernel_launch(void* const* d_in, const int* in_sizes, int n_in,
                              void* d_out, int out_size)
{
    const int*   loop  = (const int*)  d_in[0];
    const float* edge  = (const float*)d_in[2];
    const float* face  = (const float*)d_in[3];
    const float* w_in1  = (const float*)d_in[4];
    const float* b_in1  = (const float*)d_in[5];
    const float* w_out1 = (const float*)d_in[6];
    const float* b_out1 = (const float*)d_in[7];
    const float* ln1_g  = (const float*)d_in[8];
    const float* ln1_b  = (const float*)d_in[9];
    const float* w_in2  = (const float*)d_in[10];
    const float* b_in2  = (const float*)d_in[11];
    const float* w_out2 = (const float*)d_in[12];
    const float* b_out2 = (const float*)d_in[13];
    const float* ln2_g  = (const float*)d_in[14];
    const float* ln2_b  = (const float*)d_in[15];

    float *X;
    half_t *Q, *KV, *Ac, *Ec, *ATTc, *Wc1, *Wc2, *Wo1, *Wo2;
    cudaGetSymbolAddress((void**)&Q,    g_Q);
    cudaGetSymbolAddress((void**)&KV,   g_KV);
    cudaGetSymbolAddress((void**)&X,    g_X);
    cudaGetSymbolAddress((void**)&Ac,   g_Ac);
    cudaGetSymbolAddress((void**)&Ec,   g_Ec);
    cudaGetSymbolAddress((void**)&ATTc, g_ATTc);
    cudaGetSymbolAddress((void**)&Wc1,  g_Wc1);
    cudaGetSymbolAddress((void**)&Wc2,  g_Wc2);
    cudaGetSymbolAddress((void**)&Wo1,  g_Wo1);
    cudaGetSymbolAddress((void**)&Wo2,  g_Wo2);

    cudaFuncSetAttribute(qkv_mma,   cudaFuncAttributeMaxDynamicSharedMemorySize, SMEM_QKV);
    cudaFuncSetAttribute(outln_mma, cudaFuncAttributeMaxDynamicSharedMemorySize, SMEM_OUT);

    conv_all<<<2304, 256>>>(face, edge, w_in1, w_out1, w_in2, w_out2,
                            Ac, Ec, Wc1, Wo1, Wc2, Wo2);

    // ---- layer 1 ----
    qkv_mma    <<<384, 256, SMEM_QKV>>>(Ac, Ec, Wc1, b_in1, Q, KV);
    attn_kernel<<<1024, 256>>>(loop, Q, KV, ATTc);
    outln_mma  <<<128, 256, SMEM_OUT>>>(ATTc, Wo1, b_out1, face, ln1_g, ln1_b, X, Ac);

    // ---- layer 2 ----
    qkv_mma    <<<384, 256, SMEM_QKV>>>(Ac, Ec, Wc2, b_in2, Q, KV);
    attn_kernel<<<1024, 256>>>(loop, Q, KV, ATTc);
    outln_mma  <<<128, 256, SMEM_OUT>>>(ATTc, Wo2, b_out2, X, ln2_g, ln2_b,
                                        (float*)d_out, (half_t*)nullptr);
}